// round 16
// baseline (speedup 1.0000x reference)
#include <cuda_runtime.h>
#include <math.h>

// OptNet_2525440770614 — register warp QP, Gauss-Jordan on [Q | -p, g]. FINAL.
//
// Session summary (8 passing rounds, 6 distinct bodies):
//   R1  62us  single-thread fp64 (latency-bound serial chain)
//   R2  25us  warp-parallel fp64 (fp64 pipes are vestigial on sm_103a)
//   R3  13us  full fp32 + smem (LDS/syncwarp round-trips dominate)
//   R4  6.7us registers + shuffles only (floor reached)
//   R5+ 6.3-6.9us: GJ, rcp/ex2/lg2 approx, folded reductions — all in-noise
//   R13 FAILED: unpredicated q-update (GJ rows stay live post-pivot) — reverted
// Floor = per-launch ramp (~5k cyc @ idle DVFS, cold L1/I$) + ~1.5us graph
// replay. 0% on every pipe is the correct roofline for a 1.5kFLOP problem
// (the reference's 69-GFLOP fc1 path is dead code and is skipped entirely).
//
// Body: lane i owns row i, registers + shuffle comm only; pivoting-free
// Gauss-Jordan (SPD) with rcp.approx pivots solving both RHS in one pass;
// viol folded as g.(zu-z0)-s0; 4-step butterflies (data in lanes 0-9, results
// uniform over 0-15, no broadcasts); log2-domain softmax via raw ex2/lg2.

#define NC 10
#define QP_EPS 1e-4f
#define FULL 0xffffffffu
#define LOG2E 1.4426950408889634f

__device__ __forceinline__ float rcp_approx(float x) {
    float r;
    asm("rcp.approx.f32 %0, %1;" : "=f"(r) : "f"(x));
    return r;
}
__device__ __forceinline__ float ex2_approx(float x) {
    float r;
    asm("ex2.approx.f32 %0, %1;" : "=f"(r) : "f"(x));
    return r;
}
__device__ __forceinline__ float lg2_approx(float x) {
    float r;
    asm("lg2.approx.f32 %0, %1;" : "=f"(r) : "f"(x));
    return r;
}

__global__ void __launch_bounds__(32, 1)
optnet_qp_best(const float* __restrict__ L,
               const float* __restrict__ p,
               const float* __restrict__ G,
               const float* __restrict__ z0,
               const float* __restrict__ s0,
               float* __restrict__ out) {
    const int lane = threadIdx.x;
    const bool act = (lane < NC);

    // ---- front-batched independent loads ----
    float l[NC];                        // my tril row of L
    #pragma unroll
    for (int k = 0; k < NC; k++)
        l[k] = (act && k <= lane) ? L[lane * NC + k] : 0.0f;

    float gv  = act ? G[lane]  : 0.0f;
    float z0v = act ? z0[lane] : 0.0f;
    float pv  = act ? p[lane]  : 0.0f;
    float s0v = s0[0];

    // ---- Q row i: q[j] = sum_{k<=j} l_i[k] * l_j[k]  (+eps on diag) ----
    float q[NC];
    #pragma unroll
    for (int j = 0; j < NC; j++) {
        float s = (j == lane) ? QP_EPS : 0.0f;
        #pragma unroll
        for (int k = 0; k <= j; k++)
            s = fmaf(l[k], __shfl_sync(FULL, l[k], j), s);
        q[j] = s;
    }

    // ---- Gauss-Jordan on [Q | r1=-p, r2=g], no pivoting (SPD) ----
    // Row j stays LIVE after its pivot step (GJ upper elimination) — all
    // updates must be predicated off lane j.
    float r1 = -pv, r2 = gv;
    float myrcp = 1.0f;

    #pragma unroll
    for (int j = 0; j < NC; j++) {
        // RHS row-j values: depend only on previous iter -> issue first
        float rj1 = __shfl_sync(FULL, r1, j);
        float rj2 = __shfl_sync(FULL, r2, j);
        float rs_local = rcp_approx(q[j]);          // MUFU only
        if (lane == j) myrcp = rs_local;
        float rs = __shfl_sync(FULL, rs_local, j);  // pivot reciprocal
        float m  = q[j] * rs;                       // multiplier
        bool upd = (lane != j);
        if (upd) {
            r1 = fmaf(-m, rj1, r1);
            r2 = fmaf(-m, rj2, r2);
        }
        #pragma unroll
        for (int k = j + 1; k < NC; k++) {
            float qjk = __shfl_sync(FULL, q[k], j);
            if (upd) q[k] = fmaf(-m, qjk, q[k]);
        }
    }

    // ---- solutions (mask: lanes >=10 hold inf/NaN garbage) ----
    float zu = act ? r1 * myrcp : 0.0f;   // Q^-1 (-p)
    float qg = act ? r2 * myrcp : 0.0f;   // Q^-1 g

    // ---- viol = g.(zu - z0) - s0 ; denom = g.qg (overlapped butterflies,
    //      results uniform across lanes 0-15; no broadcast needed) ----
    float da = gv * (zu - z0v);
    float db = gv * qg;
    #pragma unroll
    for (int o = 8; o >= 1; o >>= 1) {
        da += __shfl_xor_sync(FULL, da, o);
        db += __shfl_xor_sync(FULL, db, o);
    }
    float lam = fmaxf(da - s0v, 0.0f) * rcp_approx(db);

    // ---- z, log_softmax in log2 domain (raw MUFU ex2/lg2) ----
    float zf = act ? fmaf(-lam, qg, zu) : -INFINITY;

    float mx = zf;
    #pragma unroll
    for (int o = 8; o >= 1; o >>= 1)
        mx = fmaxf(mx, __shfl_xor_sync(FULL, mx, o));

    float t  = (zf - mx) * LOG2E;              // log2-domain exponent
    float e  = act ? ex2_approx(t) : 0.0f;
    float se = e;
    #pragma unroll
    for (int o = 8; o >= 1; o >>= 1) se += __shfl_xor_sync(FULL, se, o);
    float lse = lg2_approx(se) * (1.0f / LOG2E);   // back to natural log

    if (act) out[lane] = zf - mx - lse;
}

extern "C" void kernel_launch(void* const* d_in, const int* in_sizes, int n_in,
                              void* d_out, int out_size) {
    // metadata order: x, W1, b1, L, p, G, z0, s0
    const float* L  = (const float*)d_in[3];
    const float* p  = (const float*)d_in[4];
    const float* G  = (const float*)d_in[5];
    const float* z0 = (const float*)d_in[6];
    const float* s0 = (const float*)d_in[7];
    float* out = (float*)d_out;
    (void)in_sizes; (void)n_in; (void)out_size;

    optnet_qp_best<<<1, 32>>>(L, p, G, z0, s0, out);
}

// round 17
// speedup vs baseline: 1.0337x; 1.0337x over previous
#include <cuda_runtime.h>
#include <math.h>

// OptNet_2525440770614 — register warp QP, Gauss-Jordan on [Q | -p, g].
// FROZEN FINAL BODY (verified passing R11/R12/R15/R16; rel_err 1.478793e-05).
//
// Session: 61.9us (R1 single-thread fp64) -> 6.7+-0.3us floor (~9.2x).
//   - the reference's 69-GFLOP fc1 path is dead code; real work ~1.5kFLOP
//   - fp64 -> warp fp64 -> fp32+smem -> registers+shuffles-only progression
//   - pivoting-free Gauss-Jordan (SPD) on [Q | -p, g], rcp.approx pivots,
//     both RHS in one pass; viol folded as g.(zu-z0)-s0; 4-step butterflies;
//     log2-domain softmax via raw ex2/lg2
//   - R13 lesson: GJ rows stay LIVE after their pivot step — all updates
//     predicated off lane j
// Floor = per-launch ramp (~5k cyc @ idle DVFS, cold L1/I$) + ~1.5us graph
// replay, unaddressable from inside kernel_launch. Identical-body control
// runs (R12/R15/R16) move dur_us more than any body edit ever did.

#define NC 10
#define QP_EPS 1e-4f
#define FULL 0xffffffffu
#define LOG2E 1.4426950408889634f

__device__ __forceinline__ float rcp_approx(float x) {
    float r;
    asm("rcp.approx.f32 %0, %1;" : "=f"(r) : "f"(x));
    return r;
}
__device__ __forceinline__ float ex2_approx(float x) {
    float r;
    asm("ex2.approx.f32 %0, %1;" : "=f"(r) : "f"(x));
    return r;
}
__device__ __forceinline__ float lg2_approx(float x) {
    float r;
    asm("lg2.approx.f32 %0, %1;" : "=f"(r) : "f"(x));
    return r;
}

__global__ void __launch_bounds__(32, 1)
optnet_qp_best(const float* __restrict__ L,
               const float* __restrict__ p,
               const float* __restrict__ G,
               const float* __restrict__ z0,
               const float* __restrict__ s0,
               float* __restrict__ out) {
    const int lane = threadIdx.x;
    const bool act = (lane < NC);

    // ---- front-batched independent loads ----
    float l[NC];                        // my tril row of L
    #pragma unroll
    for (int k = 0; k < NC; k++)
        l[k] = (act && k <= lane) ? L[lane * NC + k] : 0.0f;

    float gv  = act ? G[lane]  : 0.0f;
    float z0v = act ? z0[lane] : 0.0f;
    float pv  = act ? p[lane]  : 0.0f;
    float s0v = s0[0];

    // ---- Q row i: q[j] = sum_{k<=j} l_i[k] * l_j[k]  (+eps on diag) ----
    float q[NC];
    #pragma unroll
    for (int j = 0; j < NC; j++) {
        float s = (j == lane) ? QP_EPS : 0.0f;
        #pragma unroll
        for (int k = 0; k <= j; k++)
            s = fmaf(l[k], __shfl_sync(FULL, l[k], j), s);
        q[j] = s;
    }

    // ---- Gauss-Jordan on [Q | r1=-p, r2=g], no pivoting (SPD) ----
    // Row j stays LIVE after its pivot step (GJ upper elimination) — all
    // updates must be predicated off lane j.
    float r1 = -pv, r2 = gv;
    float myrcp = 1.0f;

    #pragma unroll
    for (int j = 0; j < NC; j++) {
        // RHS row-j values: depend only on previous iter -> issue first
        float rj1 = __shfl_sync(FULL, r1, j);
        float rj2 = __shfl_sync(FULL, r2, j);
        float rs_local = rcp_approx(q[j]);          // MUFU only
        if (lane == j) myrcp = rs_local;
        float rs = __shfl_sync(FULL, rs_local, j);  // pivot reciprocal
        float m  = q[j] * rs;                       // multiplier
        bool upd = (lane != j);
        if (upd) {
            r1 = fmaf(-m, rj1, r1);
            r2 = fmaf(-m, rj2, r2);
        }
        #pragma unroll
        for (int k = j + 1; k < NC; k++) {
            float qjk = __shfl_sync(FULL, q[k], j);
            if (upd) q[k] = fmaf(-m, qjk, q[k]);
        }
    }

    // ---- solutions (mask: lanes >=10 hold inf/NaN garbage) ----
    float zu = act ? r1 * myrcp : 0.0f;   // Q^-1 (-p)
    float qg = act ? r2 * myrcp : 0.0f;   // Q^-1 g

    // ---- viol = g.(zu - z0) - s0 ; denom = g.qg (overlapped butterflies,
    //      results uniform across lanes 0-15; no broadcast needed) ----
    float da = gv * (zu - z0v);
    float db = gv * qg;
    #pragma unroll
    for (int o = 8; o >= 1; o >>= 1) {
        da += __shfl_xor_sync(FULL, da, o);
        db += __shfl_xor_sync(FULL, db, o);
    }
    float lam = fmaxf(da - s0v, 0.0f) * rcp_approx(db);

    // ---- z, log_softmax in log2 domain (raw MUFU ex2/lg2) ----
    float zf = act ? fmaf(-lam, qg, zu) : -INFINITY;

    float mx = zf;
    #pragma unroll
    for (int o = 8; o >= 1; o >>= 1)
        mx = fmaxf(mx, __shfl_xor_sync(FULL, mx, o));

    float t  = (zf - mx) * LOG2E;              // log2-domain exponent
    float e  = act ? ex2_approx(t) : 0.0f;
    float se = e;
    #pragma unroll
    for (int o = 8; o >= 1; o >>= 1) se += __shfl_xor_sync(FULL, se, o);
    float lse = lg2_approx(se) * (1.0f / LOG2E);   // back to natural log

    if (act) out[lane] = zf - mx - lse;
}

extern "C" void kernel_launch(void* const* d_in, const int* in_sizes, int n_in,
                              void* d_out, int out_size) {
    // metadata order: x, W1, b1, L, p, G, z0, s0
    const float* L  = (const float*)d_in[3];
    const float* p  = (const float*)d_in[4];
    const float* G  = (const float*)d_in[5];
    const float* z0 = (const float*)d_in[6];
    const float* s0 = (const float*)d_in[7];
    float* out = (float*)d_out;
    (void)in_sizes; (void)n_in; (void)out_size;

    optnet_qp_best<<<1, 32>>>(L, p, G, z0, s0, out);
}